// round 15
// baseline (speedup 1.0000x reference)
#include <cuda_runtime.h>
#include <cuda_fp16.h>
#include <stdint.h>
#include <math.h>

#define NTOK   (16 * 4096)   // 65536 tokens
#define D_IN   512
#define D_K    256
#define MSLOTS 64

// ---------------------------------------------------------------------------
// Scratch
// ---------------------------------------------------------------------------
__device__ __align__(256) __half g_E[(size_t)NTOK * D_K];     // encoded fp16
__device__ __align__(256) __half g_EW[D_K * D_IN];            // enc_w fp16
__device__ __align__(256) __half g_MEM[MSLOTS * D_K];         // mem fp16
__device__ __align__(256) __half g_MT[D_K * MSLOTS];          // mem^T fp16
__device__ __align__(256) __half g_W2T[D_IN * MSLOTS];        // (dec_w @ mem^T) fp16

// ---------------------------------------------------------------------------
// PTX helpers
// ---------------------------------------------------------------------------
__device__ __forceinline__ uint32_t smem_u32(const void* p) {
    uint32_t a;
    asm("{ .reg .u64 t; cvta.to.shared.u64 t, %1; cvt.u32.u64 %0, t; }"
        : "=r"(a) : "l"(p));
    return a;
}
__device__ __forceinline__ void cp16(uint32_t dst, const void* src) {
    asm volatile("cp.async.cg.shared.global [%0], [%1], 16;"
                 :: "r"(dst), "l"(src));
}
__device__ __forceinline__ void cp_commit() {
    asm volatile("cp.async.commit_group;");
}
__device__ __forceinline__ void cp_wait0() {
    asm volatile("cp.async.wait_group 0;" ::: "memory");
}

#define LDSM4(r0, r1, r2, r3, addr)                                            \
    asm volatile("ldmatrix.sync.aligned.m8n8.x4.shared.b16 {%0,%1,%2,%3}, [%4];" \
                 : "=r"(r0), "=r"(r1), "=r"(r2), "=r"(r3) : "r"(addr))
#define LDSM2(r0, r1, addr)                                                    \
    asm volatile("ldmatrix.sync.aligned.m8n8.x2.shared.b16 {%0,%1}, [%2];"     \
                 : "=r"(r0), "=r"(r1) : "r"(addr))
#define MMA16816(c, a, b)                                                      \
    asm volatile(                                                              \
        "mma.sync.aligned.m16n8k16.row.col.f32.f16.f16.f32 "                   \
        "{%0,%1,%2,%3},{%4,%5,%6,%7},{%8,%9},{%0,%1,%2,%3};"                   \
        : "+f"((c)[0]), "+f"((c)[1]), "+f"((c)[2]), "+f"((c)[3])               \
        : "r"((a)[0]), "r"((a)[1]), "r"((a)[2]), "r"((a)[3]),                  \
          "r"((b)[0]), "r"((b)[1]))

// ---------------------------------------------------------------------------
// K1: encoded = tanh(seq @ enc_w^T + enc_b). seq fp32 converted in-kernel.
// (unchanged passing version)
// ---------------------------------------------------------------------------
__global__ __launch_bounds__(256, 2)
void gemm_enc(const float* __restrict__ A,
              const __half* __restrict__ B,
              const float* __restrict__ bias,
              __half* __restrict__ E)
{
    constexpr int AF32_BYTES = 128 * 144;
    constexpr int B_BYTES    = 128 * 80;
    constexpr int OFF_AF = 0;
    constexpr int OFF_B  = 2 * AF32_BYTES;
    constexpr int OFF_AH = OFF_B + 2 * B_BYTES;

    extern __shared__ char smem[];
    const uint32_t sb = smem_u32(smem);
    const int tid = threadIdx.x, lane = tid & 31, wid = tid >> 5;
    const int wm = wid & 1, wn = wid >> 1;
    const int m0 = blockIdx.y * 128;
    const int n0 = blockIdx.x * 128;

    float c[4][4][4];
#pragma unroll
    for (int mi = 0; mi < 4; mi++)
#pragma unroll
        for (int ni = 0; ni < 4; ni++)
#pragma unroll
            for (int j = 0; j < 4; j++) c[mi][ni][j] = 0.f;

    auto load_chunk = [&](int ch) {
        const int kc = ch * 32;
        const uint32_t stA = sb + OFF_AF + (uint32_t)((ch & 1) * AF32_BYTES);
        const uint32_t stB = sb + OFF_B  + (uint32_t)((ch & 1) * B_BYTES);
#pragma unroll
        for (int i = 0; i < 4; i++) {
            int e = tid + i * 256;
            int r = e >> 3, g = e & 7;
            cp16(stA + (uint32_t)(r * 144 + g * 16),
                 A + (size_t)(m0 + r) * D_IN + kc + g * 4);
        }
#pragma unroll
        for (int i = 0; i < 2; i++) {
            int e = tid + i * 256;
            int r = e >> 2, g = e & 3;
            cp16(stB + (uint32_t)(r * 80 + g * 16),
                 B + (size_t)(n0 + r) * D_IN + kc + g * 8);
        }
        cp_commit();
    };

    load_chunk(0);

    const uint32_t aRow = (uint32_t)((wm * 64 + (lane & 15)) * 80 + (lane >> 4) * 16);
    const uint32_t bRow = (uint32_t)((wn * 32 + (lane & 7)) * 80 + ((lane >> 3) & 1) * 16);
    const int cr  = tid & 127;
    const int chf = tid >> 7;

    for (int ch = 0; ch < 16; ch++) {
        cp_wait0();
        __syncthreads();

        {
            const char* src = smem + OFF_AF + (ch & 1) * AF32_BYTES
                            + cr * 144 + chf * 64;
            float4 f0 = *(const float4*)(src);
            float4 f1 = *(const float4*)(src + 16);
            float4 f2 = *(const float4*)(src + 32);
            float4 f3 = *(const float4*)(src + 48);
            __half2 h[8];
            h[0] = __floats2half2_rn(f0.x, f0.y);
            h[1] = __floats2half2_rn(f0.z, f0.w);
            h[2] = __floats2half2_rn(f1.x, f1.y);
            h[3] = __floats2half2_rn(f1.z, f1.w);
            h[4] = __floats2half2_rn(f2.x, f2.y);
            h[5] = __floats2half2_rn(f2.z, f2.w);
            h[6] = __floats2half2_rn(f3.x, f3.y);
            h[7] = __floats2half2_rn(f3.z, f3.w);
            uint4* dst = (uint4*)(smem + OFF_AH + cr * 80 + chf * 32);
            uint4 u0, u1;
            u0.x = *(uint32_t*)&h[0]; u0.y = *(uint32_t*)&h[1];
            u0.z = *(uint32_t*)&h[2]; u0.w = *(uint32_t*)&h[3];
            u1.x = *(uint32_t*)&h[4]; u1.y = *(uint32_t*)&h[5];
            u1.z = *(uint32_t*)&h[6]; u1.w = *(uint32_t*)&h[7];
            dst[0] = u0; dst[1] = u1;
        }

        if (ch + 1 < 16) load_chunk(ch + 1);
        __syncthreads();

        const uint32_t stB = sb + OFF_B + (uint32_t)((ch & 1) * B_BYTES);
#pragma unroll
        for (int kk = 0; kk < 2; kk++) {
            uint32_t a[4][4], b[4][2];
#pragma unroll
            for (int mi = 0; mi < 4; mi++) {
                uint32_t ad = sb + OFF_AH + aRow + (uint32_t)(mi * 1280 + kk * 32);
                LDSM4(a[mi][0], a[mi][1], a[mi][2], a[mi][3], ad);
            }
#pragma unroll
            for (int ni = 0; ni < 4; ni++) {
                uint32_t bd = stB + bRow + (uint32_t)(ni * 640 + kk * 32);
                LDSM2(b[ni][0], b[ni][1], bd);
            }
#pragma unroll
            for (int mi = 0; mi < 4; mi++)
#pragma unroll
                for (int ni = 0; ni < 4; ni++)
                    MMA16816(c[mi][ni], a[mi], b[ni]);
        }
    }

    const int r_in = lane >> 2, cpair = (lane & 3) * 2;
#pragma unroll
    for (int mi = 0; mi < 4; mi++) {
        const int rg = m0 + wm * 64 + mi * 16 + r_in;
#pragma unroll
        for (int ni = 0; ni < 4; ni++) {
            const int cg = n0 + wn * 32 + ni * 8 + cpair;
            float b0 = bias[cg], b1 = bias[cg + 1];
            float v0 = tanhf(c[mi][ni][0] + b0);
            float v1 = tanhf(c[mi][ni][1] + b1);
            float v2 = tanhf(c[mi][ni][2] + b0);
            float v3 = tanhf(c[mi][ni][3] + b1);
            *(__half2*)(E + (size_t)rg * D_K + cg)       = __floats2half2_rn(v0, v1);
            *(__half2*)(E + (size_t)(rg + 8) * D_K + cg) = __floats2half2_rn(v2, v3);
        }
    }
}

// ---------------------------------------------------------------------------
// K2: fused logits + softmax + memo + recon (round-14 passing version)
// ---------------------------------------------------------------------------
__global__ __launch_bounds__(256)
void attn_fused(const __half* __restrict__ E,
                const __half* __restrict__ MEMp,
                const __half* __restrict__ MTp,
                const __half* __restrict__ W2Tp,
                const float* __restrict__ dec_b,
                float* __restrict__ att,
                float* __restrict__ memo,
                float* __restrict__ recon)
{
    constexpr int A_BYTES = 10240, B1_BYTES = 64 * 80;
    constexpr int OFF_A = 0, OFF_B1 = A_BYTES;
    constexpr int STAGE1 = A_BYTES + B1_BYTES;   // 15360
    constexpr int OFF_LG  = 2 * STAGE1;          // 30720
    constexpr int OFF_AT16 = 0;
    constexpr int OFF_B2  = 30720;

    extern __shared__ char smem[];
    const uint32_t sb = smem_u32(smem);
    const int tid = threadIdx.x, lane = tid & 31, wid = tid >> 5;
    const int wm = wid & 1, wn = wid >> 1;
    const int m0 = blockIdx.x * 128;
    const int r_in = lane >> 2, cpair = (lane & 3) * 2;

    // ================= phase 1: logits =================
    float c1[4][2][4];
#pragma unroll
    for (int mi = 0; mi < 4; mi++)
#pragma unroll
        for (int ni = 0; ni < 2; ni++)
#pragma unroll
            for (int j = 0; j < 4; j++) c1[mi][ni][j] = 0.f;

    auto load_chunk1 = [&](int ch) {
        const uint32_t st = sb + (uint32_t)((ch & 1) * STAGE1);
        const int kc = ch * 32;
#pragma unroll
        for (int i = 0; i < 2; i++) {
            int e = tid + i * 256;
            int r = e >> 2, g = e & 3;
            cp16(st + OFF_A + (uint32_t)(r * 80 + g * 16),
                 E + (size_t)(m0 + r) * D_K + kc + g * 8);
        }
        {
            int r = tid >> 2, g = tid & 3;
            if (r < 64)
                cp16(st + OFF_B1 + (uint32_t)(r * 80 + g * 16),
                     MEMp + (size_t)r * D_K + kc + g * 8);
        }
        cp_commit();
    };

    load_chunk1(0);

    const uint32_t aRow1 = (uint32_t)((wm * 64 + (lane & 15)) * 80 + (lane >> 4) * 16);
    const uint32_t bRow1 = (uint32_t)((wn * 16 + (lane & 7)) * 80 + ((lane >> 3) & 1) * 16);

    for (int ch = 0; ch < 8; ch++) {
        cp_wait0();
        __syncthreads();
        if (ch + 1 < 8) load_chunk1(ch + 1);

        const uint32_t st = sb + (uint32_t)((ch & 1) * STAGE1);
#pragma unroll
        for (int kk = 0; kk < 2; kk++) {
            uint32_t a[4][4], b[2][2];
#pragma unroll
            for (int mi = 0; mi < 4; mi++) {
                uint32_t ad = st + OFF_A + aRow1 + (uint32_t)(mi * 1280 + kk * 32);
                LDSM4(a[mi][0], a[mi][1], a[mi][2], a[mi][3], ad);
            }
#pragma unroll
            for (int ni = 0; ni < 2; ni++) {
                uint32_t bd = st + OFF_B1 + bRow1 + (uint32_t)(ni * 640 + kk * 32);
                LDSM2(b[ni][0], b[ni][1], bd);
            }
#pragma unroll
            for (int mi = 0; mi < 4; mi++)
#pragma unroll
                for (int ni = 0; ni < 2; ni++)
                    MMA16816(c1[mi][ni], a[mi], b[ni]);
        }
        __syncthreads();
    }

    float* LGf = (float*)(smem + OFF_LG);
#pragma unroll
    for (int mi = 0; mi < 4; mi++) {
        const int rl = wm * 64 + mi * 16 + r_in;
#pragma unroll
        for (int ni = 0; ni < 2; ni++) {
            const int cl = wn * 16 + ni * 8 + cpair;
            LGf[rl * 68 + cl]           = c1[mi][ni][0] * 0.0625f;
            LGf[rl * 68 + cl + 1]       = c1[mi][ni][1] * 0.0625f;
            LGf[(rl + 8) * 68 + cl]     = c1[mi][ni][2] * 0.0625f;
            LGf[(rl + 8) * 68 + cl + 1] = c1[mi][ni][3] * 0.0625f;
        }
    }
    __syncthreads();

    {
        const int row = tid >> 1, half = tid & 1;
        float* lr = LGf + row * 68 + half * 32;
        float mx = lr[0];
#pragma unroll 8
        for (int j = 1; j < 32; j++) mx = fmaxf(mx, lr[j]);
        mx = fmaxf(mx, __shfl_xor_sync(0xffffffffu, mx, 1));
        float sum = 0.f;
#pragma unroll 8
        for (int j = 0; j < 32; j++) {
            float p = expf(lr[j] - mx);
            lr[j] = p;
            sum += p;
        }
        sum += __shfl_xor_sync(0xffffffffu, sum, 1);
        float inv = 1.f / sum;
#pragma unroll 8
        for (int j = 0; j < 32; j++) lr[j] *= inv;
    }
    __syncthreads();

#pragma unroll
    for (int i = 0; i < 32; i++) {
        int idx = tid + i * 256;
        int r = idx >> 6, cc = idx & 63;
        float v = LGf[r * 68 + cc];
        att[(size_t)(m0 + r) * 64 + cc] = v;
        *(__half*)(smem + OFF_AT16 + r * 144 + cc * 2) = __float2half_rn(v);
    }
    __syncthreads();

    // ================= phase 2: memo + recon =================
    auto load_B2 = [&](int j) {
        if (j < 6) {
            const uint32_t st = sb + OFF_B2 + (uint32_t)((j & 1) * 18432);
            const __half* src = (j < 2) ? (MTp + (size_t)(j * 128) * MSLOTS)
                                        : (W2Tp + (size_t)((j - 2) * 128) * MSLOTS);
#pragma unroll
            for (int i = 0; i < 4; i++) {
                int e = tid + i * 256;
                int r = e >> 3, g = e & 7;
                cp16(st + (uint32_t)(r * 144 + g * 16),
                     src + (size_t)r * MSLOTS + g * 8);
            }
            cp_commit();
        }
    };

    load_B2(0);

    const uint32_t aRow2 = (uint32_t)((wm * 64 + (lane & 15)) * 144 + (lane >> 4) * 16);
    const uint32_t bRow2 = (uint32_t)((wn * 32 + (lane & 7)) * 144 + ((lane >> 3) & 1) * 16);

    for (int j = 0; j < 6; j++) {
        cp_wait0();
        __syncthreads();
        load_B2(j + 1);

        float c2[4][4][4];
#pragma unroll
        for (int mi = 0; mi < 4; mi++)
#pragma unroll
            for (int ni = 0; ni < 4; ni++)
#pragma unroll
                for (int q = 0; q < 4; q++) c2[mi][ni][q] = 0.f;

        const uint32_t stB = sb + OFF_B2 + (uint32_t)((j & 1) * 18432);
#pragma unroll
        for (int kk = 0; kk < 4; kk++) {
            uint32_t a[4][4], b[4][2];
#pragma unroll
            for (int mi = 0; mi < 4; mi++) {
                uint32_t ad = sb + OFF_AT16 + aRow2 + (uint32_t)(mi * 2304 + kk * 32);
                LDSM4(a[mi][0], a[mi][1], a[mi][2], a[mi][3], ad);
            }
#pragma unroll
            for (int ni = 0; ni < 4; ni++) {
                uint32_t bd = stB + bRow2 + (uint32_t)(ni * 1152 + kk * 32);
                LDSM2(b[ni][0], b[ni][1], bd);
            }
#pragma unroll
            for (int mi = 0; mi < 4; mi++)
#pragma unroll
                for (int ni = 0; ni < 4; ni++)
                    MMA16816(c2[mi][ni], a[mi], b[ni]);
        }

        const bool is_memo = (j < 2);
        float* Cf = is_memo ? memo : recon;
        const int Ntot = is_memo ? D_K : D_IN;
        const int n0 = (is_memo ? j : (j - 2)) * 128;
#pragma unroll
        for (int mi = 0; mi < 4; mi++) {
            const int rg = m0 + wm * 64 + mi * 16 + r_in;
#pragma unroll
            for (int ni = 0; ni < 4; ni++) {
                const int cg = n0 + wn * 32 + ni * 8 + cpair;
                float v0 = c2[mi][ni][0], v1 = c2[mi][ni][1];
                float v2 = c2[mi][ni][2], v3 = c2[mi][ni][3];
                if (!is_memo) {
                    float b0 = dec_b[cg], b1 = dec_b[cg + 1];
                    v0 += b0; v1 += b1; v2 += b0; v3 += b1;
                }
                *(float2*)(Cf + (size_t)rg * Ntot + cg)       = make_float2(v0, v1);
                *(float2*)(Cf + (size_t)(rg + 8) * Ntot + cg) = make_float2(v2, v3);
            }
        }
    }
}

// ---------------------------------------------------------------------------
// Prep: blocks [0, CVT_BLOCKS) do element-wise conversions;
//       blocks [CVT_BLOCKS, ...) do W2T with one WARP per output
//       (coalesced stride-32 reads + shuffle reduce).
// ---------------------------------------------------------------------------
#define CVT_ITEMS   (32768 + 4096 + 16384)     // 53248
#define CVT_BLOCKS  ((CVT_ITEMS + 255) / 256)  // 208
#define W2T_BLOCKS  (D_IN * MSLOTS / 8)        // 4096 (8 warps/block)

__global__ void prep_weights(const float* __restrict__ enc_w,
                             const float* __restrict__ mem,
                             const float* __restrict__ dec_w,
                             __half2* __restrict__ EW,
                             __half2* __restrict__ MEM2,
                             __half* __restrict__ MT,
                             __half* __restrict__ W2T)
{
    if (blockIdx.x < CVT_BLOCKS) {
        int i = blockIdx.x * 256 + threadIdx.x;
        if (i < 32768) {
            float4 v = ((const float4*)enc_w)[i];
            EW[2*i]   = __floats2half2_rn(v.x, v.y);
            EW[2*i+1] = __floats2half2_rn(v.z, v.w);
        } else if (i < 32768 + 4096) {
            int j = i - 32768;
            float4 v = ((const float4*)mem)[j];
            MEM2[2*j]   = __floats2half2_rn(v.x, v.y);
            MEM2[2*j+1] = __floats2half2_rn(v.z, v.w);
        } else if (i < 32768 + 4096 + 16384) {
            int j = i - 32768 - 4096;
            int r = j >> 8, cc = j & 255;
            MT[(size_t)cc * MSLOTS + r] = __float2half_rn(mem[j]);
        }
    } else {
        // W2T[d, m] = sum_k dec_w[d,k] * mem[m,k]; warp per output
        int w = (blockIdx.x - CVT_BLOCKS) * 8 + (threadIdx.x >> 5);
        int lane = threadIdx.x & 31;
        if (w >= D_IN * MSLOTS) return;
        int d = w >> 6, m = w & 63;
        const float* dw = dec_w + (size_t)d * D_K;
        const float* mm = mem + (size_t)m * D_K;
        float s = 0.f;
#pragma unroll
        for (int k = 0; k < D_K / 32; k++)
            s += dw[lane + k * 32] * mm[lane + k * 32];
#pragma unroll
        for (int o = 16; o > 0; o >>= 1)
            s += __shfl_xor_sync(0xffffffffu, s, o);
        if (lane == 0) W2T[w] = __float2half_rn(s);
    }
}

// ---------------------------------------------------------------------------
// launch
// ---------------------------------------------------------------------------
extern "C" void kernel_launch(void* const* d_in, const int* in_sizes, int n_in,
                              void* d_out, int out_size)
{
    const float* seq   = (const float*)d_in[0];
    const float* enc_w = (const float*)d_in[1];
    const float* enc_b = (const float*)d_in[2];
    const float* mem   = (const float*)d_in[3];
    const float* dec_w = (const float*)d_in[4];
    const float* dec_b = (const float*)d_in[5];

    float* out   = (float*)d_out;
    float* recon = out;
    float* att   = out + (size_t)NTOK * D_IN;
    float* memo  = att + (size_t)NTOK * MSLOTS;

    __half *E, *EW, *MEM, *MT, *W2T;
    cudaGetSymbolAddress((void**)&E, g_E);
    cudaGetSymbolAddress((void**)&EW, g_EW);
    cudaGetSymbolAddress((void**)&MEM, g_MEM);
    cudaGetSymbolAddress((void**)&MT, g_MT);
    cudaGetSymbolAddress((void**)&W2T, g_W2T);

    const int SM_G1 = 2 * 18432 + 2 * 10240 + 10240;   // 67584
    const int SM_AF = 30720 + 2 * 18432;               // 67584
    cudaFuncSetAttribute(gemm_enc,   cudaFuncAttributeMaxDynamicSharedMemorySize, SM_G1);
    cudaFuncSetAttribute(attn_fused, cudaFuncAttributeMaxDynamicSharedMemorySize, SM_AF);

    // prep (one launch): conversions + warp-parallel W2T
    prep_weights<<<CVT_BLOCKS + W2T_BLOCKS, 256>>>(enc_w, mem, dec_w,
                                                   (__half2*)EW, (__half2*)MEM,
                                                   MT, W2T);

    // 1) encoded = tanh(seq @ enc_w^T + enc_b) -> fp16 (seq converted inline)
    {
        dim3 grid(D_K / 128, NTOK / 128);
        gemm_enc<<<grid, 256, SM_G1>>>(seq, EW, enc_b, E);
    }
    // 2) fused logits + softmax + memo + recon
    attn_fused<<<NTOK / 128, 256, SM_AF>>>(E, MEM, MT, W2T, dec_b,
                                           att, memo, recon);
}

// round 16
// speedup vs baseline: 1.4611x; 1.4611x over previous
#include <cuda_runtime.h>
#include <cuda_fp16.h>
#include <stdint.h>
#include <math.h>

#define NTOK   (16 * 4096)   // 65536 tokens
#define D_IN   512
#define D_K    256
#define MSLOTS 64

// ---------------------------------------------------------------------------
// Scratch
// ---------------------------------------------------------------------------
__device__ __align__(256) __half g_E[(size_t)NTOK * D_K];     // encoded fp16
__device__ __align__(256) __half g_EW[D_K * D_IN];            // enc_w fp16
__device__ __align__(256) __half g_MEM[MSLOTS * D_K];         // mem fp16
__device__ __align__(256) __half g_MT[D_K * MSLOTS];          // mem^T fp16
__device__ __align__(256) __half g_W2T[D_IN * MSLOTS];        // (dec_w @ mem^T) fp16

// ---------------------------------------------------------------------------
// PTX helpers
// ---------------------------------------------------------------------------
__device__ __forceinline__ uint32_t smem_u32(const void* p) {
    uint32_t a;
    asm("{ .reg .u64 t; cvta.to.shared.u64 t, %1; cvt.u32.u64 %0, t; }"
        : "=r"(a) : "l"(p));
    return a;
}
__device__ __forceinline__ void cp16(uint32_t dst, const void* src) {
    asm volatile("cp.async.cg.shared.global [%0], [%1], 16;"
                 :: "r"(dst), "l"(src));
}
__device__ __forceinline__ void cp_commit() {
    asm volatile("cp.async.commit_group;");
}
__device__ __forceinline__ void cp_wait0() {
    asm volatile("cp.async.wait_group 0;" ::: "memory");
}

#define LDSM4(r0, r1, r2, r3, addr)                                            \
    asm volatile("ldmatrix.sync.aligned.m8n8.x4.shared.b16 {%0,%1,%2,%3}, [%4];" \
                 : "=r"(r0), "=r"(r1), "=r"(r2), "=r"(r3) : "r"(addr))
#define LDSM2(r0, r1, addr)                                                    \
    asm volatile("ldmatrix.sync.aligned.m8n8.x2.shared.b16 {%0,%1}, [%2];"     \
                 : "=r"(r0), "=r"(r1) : "r"(addr))
#define MMA16816(c, a, b)                                                      \
    asm volatile(                                                              \
        "mma.sync.aligned.m16n8k16.row.col.f32.f16.f16.f32 "                   \
        "{%0,%1,%2,%3},{%4,%5,%6,%7},{%8,%9},{%0,%1,%2,%3};"                   \
        : "+f"((c)[0]), "+f"((c)[1]), "+f"((c)[2]), "+f"((c)[3])               \
        : "r"((a)[0]), "r"((a)[1]), "r"((a)[2]), "r"((a)[3]),                  \
          "r"((b)[0]), "r"((b)[1]))

// ---------------------------------------------------------------------------
// K1: encoded = tanh(seq @ enc_w^T + enc_b). seq fp32 converted in-kernel.
// (unchanged passing version)
// ---------------------------------------------------------------------------
__global__ __launch_bounds__(256, 2)
void gemm_enc(const float* __restrict__ A,
              const __half* __restrict__ B,
              const float* __restrict__ bias,
              __half* __restrict__ E)
{
    constexpr int AF32_BYTES = 128 * 144;
    constexpr int B_BYTES    = 128 * 80;
    constexpr int OFF_AF = 0;
    constexpr int OFF_B  = 2 * AF32_BYTES;
    constexpr int OFF_AH = OFF_B + 2 * B_BYTES;

    extern __shared__ char smem[];
    const uint32_t sb = smem_u32(smem);
    const int tid = threadIdx.x, lane = tid & 31, wid = tid >> 5;
    const int wm = wid & 1, wn = wid >> 1;
    const int m0 = blockIdx.y * 128;
    const int n0 = blockIdx.x * 128;

    float c[4][4][4];
#pragma unroll
    for (int mi = 0; mi < 4; mi++)
#pragma unroll
        for (int ni = 0; ni < 4; ni++)
#pragma unroll
            for (int j = 0; j < 4; j++) c[mi][ni][j] = 0.f;

    auto load_chunk = [&](int ch) {
        const int kc = ch * 32;
        const uint32_t stA = sb + OFF_AF + (uint32_t)((ch & 1) * AF32_BYTES);
        const uint32_t stB = sb + OFF_B  + (uint32_t)((ch & 1) * B_BYTES);
#pragma unroll
        for (int i = 0; i < 4; i++) {
            int e = tid + i * 256;
            int r = e >> 3, g = e & 7;
            cp16(stA + (uint32_t)(r * 144 + g * 16),
                 A + (size_t)(m0 + r) * D_IN + kc + g * 4);
        }
#pragma unroll
        for (int i = 0; i < 2; i++) {
            int e = tid + i * 256;
            int r = e >> 2, g = e & 3;
            cp16(stB + (uint32_t)(r * 80 + g * 16),
                 B + (size_t)(n0 + r) * D_IN + kc + g * 8);
        }
        cp_commit();
    };

    load_chunk(0);

    const uint32_t aRow = (uint32_t)((wm * 64 + (lane & 15)) * 80 + (lane >> 4) * 16);
    const uint32_t bRow = (uint32_t)((wn * 32 + (lane & 7)) * 80 + ((lane >> 3) & 1) * 16);
    const int cr  = tid & 127;
    const int chf = tid >> 7;

    for (int ch = 0; ch < 16; ch++) {
        cp_wait0();
        __syncthreads();

        {
            const char* src = smem + OFF_AF + (ch & 1) * AF32_BYTES
                            + cr * 144 + chf * 64;
            float4 f0 = *(const float4*)(src);
            float4 f1 = *(const float4*)(src + 16);
            float4 f2 = *(const float4*)(src + 32);
            float4 f3 = *(const float4*)(src + 48);
            __half2 h[8];
            h[0] = __floats2half2_rn(f0.x, f0.y);
            h[1] = __floats2half2_rn(f0.z, f0.w);
            h[2] = __floats2half2_rn(f1.x, f1.y);
            h[3] = __floats2half2_rn(f1.z, f1.w);
            h[4] = __floats2half2_rn(f2.x, f2.y);
            h[5] = __floats2half2_rn(f2.z, f2.w);
            h[6] = __floats2half2_rn(f3.x, f3.y);
            h[7] = __floats2half2_rn(f3.z, f3.w);
            uint4* dst = (uint4*)(smem + OFF_AH + cr * 80 + chf * 32);
            uint4 u0, u1;
            u0.x = *(uint32_t*)&h[0]; u0.y = *(uint32_t*)&h[1];
            u0.z = *(uint32_t*)&h[2]; u0.w = *(uint32_t*)&h[3];
            u1.x = *(uint32_t*)&h[4]; u1.y = *(uint32_t*)&h[5];
            u1.z = *(uint32_t*)&h[6]; u1.w = *(uint32_t*)&h[7];
            dst[0] = u0; dst[1] = u1;
        }

        if (ch + 1 < 16) load_chunk(ch + 1);
        __syncthreads();

        const uint32_t stB = sb + OFF_B + (uint32_t)((ch & 1) * B_BYTES);
#pragma unroll
        for (int kk = 0; kk < 2; kk++) {
            uint32_t a[4][4], b[4][2];
#pragma unroll
            for (int mi = 0; mi < 4; mi++) {
                uint32_t ad = sb + OFF_AH + aRow + (uint32_t)(mi * 1280 + kk * 32);
                LDSM4(a[mi][0], a[mi][1], a[mi][2], a[mi][3], ad);
            }
#pragma unroll
            for (int ni = 0; ni < 4; ni++) {
                uint32_t bd = stB + bRow + (uint32_t)(ni * 640 + kk * 32);
                LDSM2(b[ni][0], b[ni][1], bd);
            }
#pragma unroll
            for (int mi = 0; mi < 4; mi++)
#pragma unroll
                for (int ni = 0; ni < 4; ni++)
                    MMA16816(c[mi][ni], a[mi], b[ni]);
        }
    }

    const int r_in = lane >> 2, cpair = (lane & 3) * 2;
#pragma unroll
    for (int mi = 0; mi < 4; mi++) {
        const int rg = m0 + wm * 64 + mi * 16 + r_in;
#pragma unroll
        for (int ni = 0; ni < 4; ni++) {
            const int cg = n0 + wn * 32 + ni * 8 + cpair;
            float b0 = bias[cg], b1 = bias[cg + 1];
            float v0 = tanhf(c[mi][ni][0] + b0);
            float v1 = tanhf(c[mi][ni][1] + b1);
            float v2 = tanhf(c[mi][ni][2] + b0);
            float v3 = tanhf(c[mi][ni][3] + b1);
            *(__half2*)(E + (size_t)rg * D_K + cg)       = __floats2half2_rn(v0, v1);
            *(__half2*)(E + (size_t)(rg + 8) * D_K + cg) = __floats2half2_rn(v2, v3);
        }
    }
}

// ---------------------------------------------------------------------------
// K2: fused logits + softmax + memo + recon (round-14/15 passing version)
// ---------------------------------------------------------------------------
__global__ __launch_bounds__(256)
void attn_fused(const __half* __restrict__ E,
                const __half* __restrict__ MEMp,
                const __half* __restrict__ MTp,
                const __half* __restrict__ W2Tp,
                const float* __restrict__ dec_b,
                float* __restrict__ att,
                float* __restrict__ memo,
                float* __restrict__ recon)
{
    constexpr int A_BYTES = 10240, B1_BYTES = 64 * 80;
    constexpr int OFF_A = 0, OFF_B1 = A_BYTES;
    constexpr int STAGE1 = A_BYTES + B1_BYTES;   // 15360
    constexpr int OFF_LG  = 2 * STAGE1;          // 30720
    constexpr int OFF_AT16 = 0;
    constexpr int OFF_B2  = 30720;

    extern __shared__ char smem[];
    const uint32_t sb = smem_u32(smem);
    const int tid = threadIdx.x, lane = tid & 31, wid = tid >> 5;
    const int wm = wid & 1, wn = wid >> 1;
    const int m0 = blockIdx.x * 128;
    const int r_in = lane >> 2, cpair = (lane & 3) * 2;

    // ================= phase 1: logits =================
    float c1[4][2][4];
#pragma unroll
    for (int mi = 0; mi < 4; mi++)
#pragma unroll
        for (int ni = 0; ni < 2; ni++)
#pragma unroll
            for (int j = 0; j < 4; j++) c1[mi][ni][j] = 0.f;

    auto load_chunk1 = [&](int ch) {
        const uint32_t st = sb + (uint32_t)((ch & 1) * STAGE1);
        const int kc = ch * 32;
#pragma unroll
        for (int i = 0; i < 2; i++) {
            int e = tid + i * 256;
            int r = e >> 2, g = e & 3;
            cp16(st + OFF_A + (uint32_t)(r * 80 + g * 16),
                 E + (size_t)(m0 + r) * D_K + kc + g * 8);
        }
        {
            int r = tid >> 2, g = tid & 3;
            if (r < 64)
                cp16(st + OFF_B1 + (uint32_t)(r * 80 + g * 16),
                     MEMp + (size_t)r * D_K + kc + g * 8);
        }
        cp_commit();
    };

    load_chunk1(0);

    const uint32_t aRow1 = (uint32_t)((wm * 64 + (lane & 15)) * 80 + (lane >> 4) * 16);
    const uint32_t bRow1 = (uint32_t)((wn * 16 + (lane & 7)) * 80 + ((lane >> 3) & 1) * 16);

    for (int ch = 0; ch < 8; ch++) {
        cp_wait0();
        __syncthreads();
        if (ch + 1 < 8) load_chunk1(ch + 1);

        const uint32_t st = sb + (uint32_t)((ch & 1) * STAGE1);
#pragma unroll
        for (int kk = 0; kk < 2; kk++) {
            uint32_t a[4][4], b[2][2];
#pragma unroll
            for (int mi = 0; mi < 4; mi++) {
                uint32_t ad = st + OFF_A + aRow1 + (uint32_t)(mi * 1280 + kk * 32);
                LDSM4(a[mi][0], a[mi][1], a[mi][2], a[mi][3], ad);
            }
#pragma unroll
            for (int ni = 0; ni < 2; ni++) {
                uint32_t bd = st + OFF_B1 + bRow1 + (uint32_t)(ni * 640 + kk * 32);
                LDSM2(b[ni][0], b[ni][1], bd);
            }
#pragma unroll
            for (int mi = 0; mi < 4; mi++)
#pragma unroll
                for (int ni = 0; ni < 2; ni++)
                    MMA16816(c1[mi][ni], a[mi], b[ni]);
        }
        __syncthreads();
    }

    float* LGf = (float*)(smem + OFF_LG);
#pragma unroll
    for (int mi = 0; mi < 4; mi++) {
        const int rl = wm * 64 + mi * 16 + r_in;
#pragma unroll
        for (int ni = 0; ni < 2; ni++) {
            const int cl = wn * 16 + ni * 8 + cpair;
            LGf[rl * 68 + cl]           = c1[mi][ni][0] * 0.0625f;
            LGf[rl * 68 + cl + 1]       = c1[mi][ni][1] * 0.0625f;
            LGf[(rl + 8) * 68 + cl]     = c1[mi][ni][2] * 0.0625f;
            LGf[(rl + 8) * 68 + cl + 1] = c1[mi][ni][3] * 0.0625f;
        }
    }
    __syncthreads();

    {
        const int row = tid >> 1, half = tid & 1;
        float* lr = LGf + row * 68 + half * 32;
        float mx = lr[0];
#pragma unroll 8
        for (int j = 1; j < 32; j++) mx = fmaxf(mx, lr[j]);
        mx = fmaxf(mx, __shfl_xor_sync(0xffffffffu, mx, 1));
        float sum = 0.f;
#pragma unroll 8
        for (int j = 0; j < 32; j++) {
            float p = expf(lr[j] - mx);
            lr[j] = p;
            sum += p;
        }
        sum += __shfl_xor_sync(0xffffffffu, sum, 1);
        float inv = 1.f / sum;
#pragma unroll 8
        for (int j = 0; j < 32; j++) lr[j] *= inv;
    }
    __syncthreads();

#pragma unroll
    for (int i = 0; i < 32; i++) {
        int idx = tid + i * 256;
        int r = idx >> 6, cc = idx & 63;
        float v = LGf[r * 68 + cc];
        att[(size_t)(m0 + r) * 64 + cc] = v;
        *(__half*)(smem + OFF_AT16 + r * 144 + cc * 2) = __float2half_rn(v);
    }
    __syncthreads();

    // ================= phase 2: memo + recon =================
    auto load_B2 = [&](int j) {
        if (j < 6) {
            const uint32_t st = sb + OFF_B2 + (uint32_t)((j & 1) * 18432);
            const __half* src = (j < 2) ? (MTp + (size_t)(j * 128) * MSLOTS)
                                        : (W2Tp + (size_t)((j - 2) * 128) * MSLOTS);
#pragma unroll
            for (int i = 0; i < 4; i++) {
                int e = tid + i * 256;
                int r = e >> 3, g = e & 7;
                cp16(st + (uint32_t)(r * 144 + g * 16),
                     src + (size_t)r * MSLOTS + g * 8);
            }
            cp_commit();
        }
    };

    load_B2(0);

    const uint32_t aRow2 = (uint32_t)((wm * 64 + (lane & 15)) * 144 + (lane >> 4) * 16);
    const uint32_t bRow2 = (uint32_t)((wn * 32 + (lane & 7)) * 144 + ((lane >> 3) & 1) * 16);

    for (int j = 0; j < 6; j++) {
        cp_wait0();
        __syncthreads();
        load_B2(j + 1);

        float c2[4][4][4];
#pragma unroll
        for (int mi = 0; mi < 4; mi++)
#pragma unroll
            for (int ni = 0; ni < 4; ni++)
#pragma unroll
                for (int q = 0; q < 4; q++) c2[mi][ni][q] = 0.f;

        const uint32_t stB = sb + OFF_B2 + (uint32_t)((j & 1) * 18432);
#pragma unroll
        for (int kk = 0; kk < 4; kk++) {
            uint32_t a[4][4], b[4][2];
#pragma unroll
            for (int mi = 0; mi < 4; mi++) {
                uint32_t ad = sb + OFF_AT16 + aRow2 + (uint32_t)(mi * 2304 + kk * 32);
                LDSM4(a[mi][0], a[mi][1], a[mi][2], a[mi][3], ad);
            }
#pragma unroll
            for (int ni = 0; ni < 4; ni++) {
                uint32_t bd = stB + bRow2 + (uint32_t)(ni * 1152 + kk * 32);
                LDSM2(b[ni][0], b[ni][1], bd);
            }
#pragma unroll
            for (int mi = 0; mi < 4; mi++)
#pragma unroll
                for (int ni = 0; ni < 4; ni++)
                    MMA16816(c2[mi][ni], a[mi], b[ni]);
        }

        const bool is_memo = (j < 2);
        float* Cf = is_memo ? memo : recon;
        const int Ntot = is_memo ? D_K : D_IN;
        const int n0 = (is_memo ? j : (j - 2)) * 128;
#pragma unroll
        for (int mi = 0; mi < 4; mi++) {
            const int rg = m0 + wm * 64 + mi * 16 + r_in;
#pragma unroll
            for (int ni = 0; ni < 4; ni++) {
                const int cg = n0 + wn * 32 + ni * 8 + cpair;
                float v0 = c2[mi][ni][0], v1 = c2[mi][ni][1];
                float v2 = c2[mi][ni][2], v3 = c2[mi][ni][3];
                if (!is_memo) {
                    float b0 = dec_b[cg], b1 = dec_b[cg + 1];
                    v0 += b0; v1 += b1; v2 += b0; v3 += b1;
                }
                *(float2*)(Cf + (size_t)rg * Ntot + cg)       = make_float2(v0, v1);
                *(float2*)(Cf + (size_t)(rg + 8) * Ntot + cg) = make_float2(v2, v3);
            }
        }
    }
}

// ---------------------------------------------------------------------------
// Prep: blocks [0, CVT_BLOCKS) do element-wise conversions;
//       blocks [CVT_BLOCKS, ...): W2T, one warp per (d, 8 m-slots):
//       dec_w row cached in regs, reused for 8 dot products.
// ---------------------------------------------------------------------------
#define CVT_ITEMS   (32768 + 4096 + 16384)     // 53248
#define CVT_BLOCKS  ((CVT_ITEMS + 255) / 256)  // 208
#define W2T_WARPS   (D_IN * 8)                 // 4096 warps (d x 8 m-groups)
#define W2T_BLOCKS  (W2T_WARPS / 8)            // 512

__global__ void prep_weights(const float* __restrict__ enc_w,
                             const float* __restrict__ mem,
                             const float* __restrict__ dec_w,
                             __half2* __restrict__ EW,
                             __half2* __restrict__ MEM2,
                             __half* __restrict__ MT,
                             __half* __restrict__ W2T)
{
    if (blockIdx.x < CVT_BLOCKS) {
        int i = blockIdx.x * 256 + threadIdx.x;
        if (i < 32768) {
            float4 v = ((const float4*)enc_w)[i];
            EW[2*i]   = __floats2half2_rn(v.x, v.y);
            EW[2*i+1] = __floats2half2_rn(v.z, v.w);
        } else if (i < 32768 + 4096) {
            int j = i - 32768;
            float4 v = ((const float4*)mem)[j];
            MEM2[2*j]   = __floats2half2_rn(v.x, v.y);
            MEM2[2*j+1] = __floats2half2_rn(v.z, v.w);
        } else if (i < 32768 + 4096 + 16384) {
            int j = i - 32768 - 4096;
            int r = j >> 8, cc = j & 255;
            MT[(size_t)cc * MSLOTS + r] = __float2half_rn(mem[j]);
        }
    } else {
        int wg = (blockIdx.x - CVT_BLOCKS) * 8 + (threadIdx.x >> 5);
        int lane = threadIdx.x & 31;
        int d = wg >> 3;             // 0..511
        int mgrp = wg & 7;           // 0..7 -> m = mgrp*8 + j
        const float* dw = dec_w + (size_t)d * D_K;
        float dwr[8];
#pragma unroll
        for (int k = 0; k < 8; k++) dwr[k] = dw[lane + k * 32];
#pragma unroll
        for (int j = 0; j < 8; j++) {
            int m = mgrp * 8 + j;
            const float* mm = mem + (size_t)m * D_K;
            float s = 0.f;
#pragma unroll
            for (int k = 0; k < 8; k++) s += dwr[k] * mm[lane + k * 32];
#pragma unroll
            for (int o = 16; o > 0; o >>= 1)
                s += __shfl_xor_sync(0xffffffffu, s, o);
            if (lane == 0) W2T[(size_t)d * MSLOTS + m] = __float2half_rn(s);
        }
    }
}

// ---------------------------------------------------------------------------
// launch
// ---------------------------------------------------------------------------
extern "C" void kernel_launch(void* const* d_in, const int* in_sizes, int n_in,
                              void* d_out, int out_size)
{
    const float* seq   = (const float*)d_in[0];
    const float* enc_w = (const float*)d_in[1];
    const float* enc_b = (const float*)d_in[2];
    const float* mem   = (const float*)d_in[3];
    const float* dec_w = (const float*)d_in[4];
    const float* dec_b = (const float*)d_in[5];

    float* out   = (float*)d_out;
    float* recon = out;
    float* att   = out + (size_t)NTOK * D_IN;
    float* memo  = att + (size_t)NTOK * MSLOTS;

    __half *E, *EW, *MEM, *MT, *W2T;
    cudaGetSymbolAddress((void**)&E, g_E);
    cudaGetSymbolAddress((void**)&EW, g_EW);
    cudaGetSymbolAddress((void**)&MEM, g_MEM);
    cudaGetSymbolAddress((void**)&MT, g_MT);
    cudaGetSymbolAddress((void**)&W2T, g_W2T);

    const int SM_G1 = 2 * 18432 + 2 * 10240 + 10240;   // 67584
    const int SM_AF = 30720 + 2 * 18432;               // 67584
    cudaFuncSetAttribute(gemm_enc,   cudaFuncAttributeMaxDynamicSharedMemorySize, SM_G1);
    cudaFuncSetAttribute(attn_fused, cudaFuncAttributeMaxDynamicSharedMemorySize, SM_AF);

    // prep (one launch): conversions + warp-parallel W2T (8 outputs/warp)
    prep_weights<<<CVT_BLOCKS + W2T_BLOCKS, 256>>>(enc_w, mem, dec_w,
                                                   (__half2*)EW, (__half2*)MEM,
                                                   MT, W2T);

    // 1) encoded = tanh(seq @ enc_w^T + enc_b) -> fp16 (seq converted inline)
    {
        dim3 grid(D_K / 128, NTOK / 128);
        gemm_enc<<<grid, 256, SM_G1>>>(seq, EW, enc_b, E);
    }
    // 2) fused logits + softmax + memo + recon
    attn_fused<<<NTOK / 128, 256, SM_AF>>>(E, MEM, MT, W2T, dec_b,
                                           att, memo, recon);
}